// round 1
// baseline (speedup 1.0000x reference)
#include <cuda_runtime.h>
#include <cstdint>

// ---------------------------------------------------------------------------
// LongformerAttention  B=2, S=4096, HID=1024, H=16, D=64, W=64
// Pipeline: QKV GEMMs -> banded chunk attention -> output GEMM
// All fp32. Padding of the reference (rows 4096..4159) is provably dead:
// padded queries are truncated, padded keys are masked. We compute on S=4096.
// ---------------------------------------------------------------------------

#define S_LEN   4096
#define HIDDEN  1024
#define NHEAD   16
#define HDIM    64
#define NCHUNK  64          // S_LEN / 64
#define BATCH   2
#define MROWS   (BATCH * S_LEN)   // 8192

// Scratch (static device globals are the sanctioned scratch mechanism)
__device__ float g_Q[(size_t)MROWS * HIDDEN];
__device__ float g_K[(size_t)MROWS * HIDDEN];
__device__ float g_V[(size_t)MROWS * HIDDEN];
__device__ float g_ctx[(size_t)MROWS * HIDDEN];

// ---------------------------------------------------------------------------
// GEMM: C[M,N] = A[M,K] @ B[K,N] + bias[N]
// Tile 128x64, BK=16, 256 threads, 8x4 per-thread micro-tile.
// M, N, K all divisible by tile dims here (M=8192, N=1024, K=1024).
// ---------------------------------------------------------------------------
__global__ __launch_bounds__(256) void gemm_bias_128x64(
    const float* __restrict__ A, const float* __restrict__ Bm,
    const float* __restrict__ bias, float* __restrict__ C,
    int K, int N)
{
    __shared__ float As[16][132];   // transposed A tile: As[k][row]
    __shared__ float Bs[16][68];    // Bs[k][col]

    const int tid  = threadIdx.x;
    const int tx   = tid & 15;       // 0..15 -> 4 cols
    const int ty   = tid >> 4;       // 0..15 -> 8 rows
    const int brow = blockIdx.y * 128;
    const int bcol = blockIdx.x * 64;

    float acc[8][4];
#pragma unroll
    for (int i = 0; i < 8; i++)
#pragma unroll
        for (int j = 0; j < 4; j++) acc[i][j] = 0.f;

    for (int k0 = 0; k0 < K; k0 += 16) {
        // load A tile: 128 rows x 16 k = 512 float4, 2 per thread
#pragma unroll
        for (int it = 0; it < 2; it++) {
            int idx = tid + it * 256;          // 0..511
            int r  = idx >> 2;                 // 0..127
            int kc = (idx & 3) << 2;           // 0,4,8,12
            float4 v = *(const float4*)(A + (size_t)(brow + r) * K + k0 + kc);
            As[kc + 0][r] = v.x;
            As[kc + 1][r] = v.y;
            As[kc + 2][r] = v.z;
            As[kc + 3][r] = v.w;
        }
        // load B tile: 16 x 64 = 256 float4? no: 1024 floats = 256 float4, 1 per thread
        {
            int r  = tid >> 4;                 // 0..15
            int nc = (tid & 15) << 2;          // 0..60
            float4 v = *(const float4*)(Bm + (size_t)(k0 + r) * N + bcol + nc);
            *(float4*)&Bs[r][nc] = v;
        }
        __syncthreads();

#pragma unroll
        for (int k = 0; k < 16; k++) {
            float a[8], bb[4];
            *(float4*)&a[0] = *(const float4*)&As[k][ty * 8];
            *(float4*)&a[4] = *(const float4*)&As[k][ty * 8 + 4];
            *(float4*)&bb[0] = *(const float4*)&Bs[k][tx * 4];
#pragma unroll
            for (int i = 0; i < 8; i++)
#pragma unroll
                for (int j = 0; j < 4; j++)
                    acc[i][j] += a[i] * bb[j];
        }
        __syncthreads();
    }

    float4 bv = *(const float4*)(bias + bcol + tx * 4);
#pragma unroll
    for (int i = 0; i < 8; i++) {
        float4 o;
        o.x = acc[i][0] + bv.x;
        o.y = acc[i][1] + bv.y;
        o.z = acc[i][2] + bv.z;
        o.w = acc[i][3] + bv.w;
        *(float4*)(C + (size_t)(brow + ty * 8 + i) * N + bcol + tx * 4) = o;
    }
}

// ---------------------------------------------------------------------------
// Banded attention. One block per (chunk c, head h, batch b).
// 64 queries x 192 keys (chunks c-1,c,c+1) x 64 dim.
// 256 threads: thread = (q = tid>>2, j = tid&3); thread j handles keys
// k = 4*kk + j (interleaved -> conflict-free padded smem access).
// Band: q <= k <= q+128 ; key valid iff 0 <= c*64-64+k < 4096 and mask>0.
// ---------------------------------------------------------------------------
#define PADW 68
#define ATTN_SMEM_FLOATS (64*PADW + 2*192*PADW + 192)

__global__ __launch_bounds__(256) void attn_kernel(const float* __restrict__ maskp)
{
    extern __shared__ float sm[];
    float* Qs  = sm;                       // 64 x 68
    float* Ks  = Qs + 64 * PADW;           // 192 x 68
    float* Vs  = Ks + 192 * PADW;          // 192 x 68
    float* vld = Vs + 192 * PADW;          // 192

    const int c = blockIdx.x;
    const int h = blockIdx.y;
    const int b = blockIdx.z;
    const int tid = threadIdx.x;

    const size_t headoff = (size_t)h * HDIM;
    const size_t bbase   = (size_t)b * S_LEN;

    // ---- load Q tile: 64 rows x 64 = 1024 float4
#pragma unroll
    for (int it = 0; it < 4; it++) {
        int idx = tid + it * 256;          // 0..1023
        int r  = idx >> 4;                 // 0..63
        int c4 = (idx & 15) << 2;          // 0..60
        float4 v = *(const float4*)(g_Q + (bbase + c * 64 + r) * HIDDEN + headoff + c4);
        *(float4*)&Qs[r * PADW + c4] = v;
    }
    // ---- load K/V tiles: 192 rows x 64 = 3072 float4 each
    const int base = c * 64 - 64;
#pragma unroll
    for (int it = 0; it < 12; it++) {
        int idx = tid + it * 256;          // 0..3071
        int r  = idx >> 4;                 // 0..191
        int c4 = (idx & 15) << 2;
        int jg = base + r;
        float4 kv = make_float4(0.f, 0.f, 0.f, 0.f);
        float4 vv = kv;
        if (jg >= 0 && jg < S_LEN) {
            size_t off = (bbase + jg) * HIDDEN + headoff + c4;
            kv = *(const float4*)(g_K + off);
            vv = *(const float4*)(g_V + off);
        }
        *(float4*)&Ks[r * PADW + c4] = kv;
        *(float4*)&Vs[r * PADW + c4] = vv;
    }
    if (tid < 192) {
        int jg = base + tid;
        vld[tid] = (jg >= 0 && jg < S_LEN && maskp[b * S_LEN + jg] > 0.f) ? 1.f : 0.f;
    }
    __syncthreads();

    const int q = tid >> 2;
    const int j = tid & 3;

    // ---- scores: sc[kk] = Q[q] . K[4kk+j]
    float sc[48];
#pragma unroll
    for (int kk = 0; kk < 48; kk++) sc[kk] = 0.f;

    const float* Qr = &Qs[q * PADW];
#pragma unroll
    for (int d4 = 0; d4 < 16; d4++) {
        float4 qv = *(const float4*)&Qr[d4 * 4];
#pragma unroll
        for (int kk = 0; kk < 48; kk++) {
            float4 kv = *(const float4*)&Ks[(kk * 4 + j) * PADW + d4 * 4];
            sc[kk] += qv.x * kv.x + qv.y * kv.y + qv.z * kv.z + qv.w * kv.w;
        }
    }

    // ---- mask + softmax (reduce across the 4 threads of a q-group)
    float m = -1e30f;
#pragma unroll
    for (int kk = 0; kk < 48; kk++) {
        int ki = kk * 4 + j;
        bool ok = (ki >= q) && (ki <= q + 128) && (vld[ki] > 0.f);
        sc[kk] = ok ? sc[kk] * 0.125f : -1e9f;
        m = fmaxf(m, sc[kk]);
    }
    m = fmaxf(m, __shfl_xor_sync(0xffffffffu, m, 1));
    m = fmaxf(m, __shfl_xor_sync(0xffffffffu, m, 2));

    float s = 0.f;
#pragma unroll
    for (int kk = 0; kk < 48; kk++) {
        sc[kk] = __expf(sc[kk] - m);       // invalid -> exp(~-1e9) -> 0
        s += sc[kk];
    }
    s += __shfl_xor_sync(0xffffffffu, s, 1);
    s += __shfl_xor_sync(0xffffffffu, s, 2);
    const float rinv = 1.f / s;

    // ---- ctx = P @ V (unnormalized, scale at the end)
    float ctx[64];
#pragma unroll
    for (int d = 0; d < 64; d++) ctx[d] = 0.f;

#pragma unroll
    for (int kk = 0; kk < 48; kk++) {
        float p = sc[kk];
        const float* Vr = &Vs[(kk * 4 + j) * PADW];
#pragma unroll
        for (int d4 = 0; d4 < 16; d4++) {
            float4 vv = *(const float4*)&Vr[d4 * 4];
            ctx[d4 * 4 + 0] += p * vv.x;
            ctx[d4 * 4 + 1] += p * vv.y;
            ctx[d4 * 4 + 2] += p * vv.z;
            ctx[d4 * 4 + 3] += p * vv.w;
        }
    }

    // ---- reduce across 4 threads; thread j owns d in [16j, 16j+16)
    float outv[16];
#pragma unroll
    for (int g = 0; g < 4; g++) {
#pragma unroll
        for (int t = 0; t < 16; t++) {
            float v = ctx[g * 16 + t];
            v += __shfl_xor_sync(0xffffffffu, v, 1);
            v += __shfl_xor_sync(0xffffffffu, v, 2);
            if (j == g) outv[t] = v * rinv;
        }
    }

    float* Og = g_ctx + (bbase + c * 64 + q) * HIDDEN + headoff + j * 16;
#pragma unroll
    for (int t4 = 0; t4 < 4; t4++)
        *(float4*)(Og + t4 * 4) = make_float4(outv[t4 * 4 + 0], outv[t4 * 4 + 1],
                                              outv[t4 * 4 + 2], outv[t4 * 4 + 3]);
}

// ---------------------------------------------------------------------------
extern "C" void kernel_launch(void* const* d_in, const int* in_sizes, int n_in,
                              void* d_out, int out_size)
{
    const float* X    = (const float*)d_in[0];
    const float* mask = (const float*)d_in[1];
    const float* Wq   = (const float*)d_in[2];
    const float* bq   = (const float*)d_in[3];
    const float* Wk   = (const float*)d_in[4];
    const float* bk   = (const float*)d_in[5];
    const float* Wv   = (const float*)d_in[6];
    const float* bv   = (const float*)d_in[7];
    const float* Wo   = (const float*)d_in[8];
    const float* bo   = (const float*)d_in[9];
    float* out = (float*)d_out;

    float *qp, *kp, *vp, *cp;
    cudaGetSymbolAddress((void**)&qp, g_Q);
    cudaGetSymbolAddress((void**)&kp, g_K);
    cudaGetSymbolAddress((void**)&vp, g_V);
    cudaGetSymbolAddress((void**)&cp, g_ctx);

    const int attn_smem = ATTN_SMEM_FLOATS * (int)sizeof(float);
    cudaFuncSetAttribute(attn_kernel, cudaFuncAttributeMaxDynamicSharedMemorySize,
                         attn_smem);

    dim3 ggrid(HIDDEN / 64, MROWS / 128);      // 16 x 64
    dim3 gblk(256);

    // QKV projections
    gemm_bias_128x64<<<ggrid, gblk>>>(X, Wq, bq, qp, HIDDEN, HIDDEN);
    gemm_bias_128x64<<<ggrid, gblk>>>(X, Wk, bk, kp, HIDDEN, HIDDEN);
    gemm_bias_128x64<<<ggrid, gblk>>>(X, Wv, bv, vp, HIDDEN, HIDDEN);

    // Banded attention
    dim3 agrid(NCHUNK, NHEAD, BATCH);          // 64 x 16 x 2
    attn_kernel<<<agrid, gblk, attn_smem>>>(mask);

    // Output projection
    gemm_bias_128x64<<<ggrid, gblk>>>(cp, Wo, bo, out, HIDDEN, HIDDEN);
}

// round 2
// speedup vs baseline: 2.0200x; 2.0200x over previous
#include <cuda_runtime.h>
#include <cstdint>

// ---------------------------------------------------------------------------
// LongformerAttention  B=2, S=4096, HID=1024, H=16, D=64, W=64
// Round 2: tf32 mma.sync GEMMs (tensor pipe) + attention smem overlay (2 blk/SM)
// ---------------------------------------------------------------------------

#define S_LEN   4096
#define HIDDEN  1024
#define NHEAD   16
#define HDIM    64
#define NCHUNK  64
#define BATCH   2
#define MROWS   (BATCH * S_LEN)   // 8192

__device__ float g_Q[(size_t)MROWS * HIDDEN];
__device__ float g_K[(size_t)MROWS * HIDDEN];
__device__ float g_V[(size_t)MROWS * HIDDEN];
__device__ float g_ctx[(size_t)MROWS * HIDDEN];

__device__ __forceinline__ float to_tf32(float x) {
    float y;
    asm("cvt.rna.tf32.f32 %0, %1;" : "=f"(y) : "f"(x));
    return y;
}

__device__ __forceinline__ void mma_tf32(float c[4], const uint32_t a[4], const uint32_t b[2]) {
    asm volatile(
        "mma.sync.aligned.m16n8k8.row.col.f32.tf32.tf32.f32 "
        "{%0,%1,%2,%3}, {%4,%5,%6,%7}, {%8,%9}, {%0,%1,%2,%3};"
        : "+f"(c[0]), "+f"(c[1]), "+f"(c[2]), "+f"(c[3])
        : "r"(a[0]), "r"(a[1]), "r"(a[2]), "r"(a[3]), "r"(b[0]), "r"(b[1]));
}

// ---------------------------------------------------------------------------
// tf32 GEMM: C[M,N] = A[M,K] @ B[K,N] + bias[N]
// Block tile 128x128, BK=32, 256 threads (8 warps, 2x4), warp tile 64x32.
// As[m][k] stride 36 (bank = 4m+k, bijective), Bs[k][n] stride 136 (bank = 8k+n).
// ---------------------------------------------------------------------------
#define GK 1024
#define GN 1024

__device__ __forceinline__ void gemm_body(
    const float* __restrict__ A, const float* __restrict__ Bm,
    const float* __restrict__ bias, float* __restrict__ C)
{
    __shared__ float As[128 * 36];
    __shared__ float Bs[32 * 136];

    const int tid  = threadIdx.x;
    const int lane = tid & 31;
    const int wid  = tid >> 5;
    const int wm   = wid >> 2;      // 0..1
    const int wn   = wid & 3;       // 0..3
    const int brow = blockIdx.y * 128;
    const int bcol = blockIdx.x * 128;

    float acc[4][4][4];
#pragma unroll
    for (int i = 0; i < 4; i++)
#pragma unroll
        for (int j = 0; j < 4; j++)
#pragma unroll
            for (int t = 0; t < 4; t++) acc[i][j][t] = 0.f;

    const int la_r  = tid >> 3;            // 0..31? no: (tid + 256i)>>3
    const int la_c4 = (tid & 7) << 2;
    const int lb_c4 = (tid & 31) << 2;

    for (int k0 = 0; k0 < GK; k0 += 32) {
        // A tile: 128 x 32 = 1024 float4, 4 per thread
#pragma unroll
        for (int i = 0; i < 4; i++) {
            int r = la_r + i * 32;
            float4 v = *(const float4*)(A + (size_t)(brow + r) * GK + k0 + la_c4);
            float* p = &As[r * 36 + la_c4];
            p[0] = to_tf32(v.x); p[1] = to_tf32(v.y);
            p[2] = to_tf32(v.z); p[3] = to_tf32(v.w);
        }
        // B tile: 32 x 128 = 1024 float4, 4 per thread
#pragma unroll
        for (int i = 0; i < 4; i++) {
            int idx = tid + i * 256;
            int kr = idx >> 5;
            float4 v = *(const float4*)(Bm + (size_t)(k0 + kr) * GN + bcol + lb_c4);
            float* p = &Bs[kr * 136 + lb_c4];
            p[0] = to_tf32(v.x); p[1] = to_tf32(v.y);
            p[2] = to_tf32(v.z); p[3] = to_tf32(v.w);
        }
        __syncthreads();

#pragma unroll
        for (int ks = 0; ks < 4; ks++) {
            const int kb = ks * 8;
            uint32_t afr[4][4];
#pragma unroll
            for (int mt = 0; mt < 4; mt++) {
                int r0 = wm * 64 + mt * 16 + (lane >> 2);
                afr[mt][0] = __float_as_uint(As[r0 * 36 + kb + (lane & 3)]);
                afr[mt][1] = __float_as_uint(As[(r0 + 8) * 36 + kb + (lane & 3)]);
                afr[mt][2] = __float_as_uint(As[r0 * 36 + kb + (lane & 3) + 4]);
                afr[mt][3] = __float_as_uint(As[(r0 + 8) * 36 + kb + (lane & 3) + 4]);
            }
            uint32_t bfr[4][2];
#pragma unroll
            for (int nt = 0; nt < 4; nt++) {
                int cN = wn * 32 + nt * 8 + (lane >> 2);
                bfr[nt][0] = __float_as_uint(Bs[(kb + (lane & 3)) * 136 + cN]);
                bfr[nt][1] = __float_as_uint(Bs[(kb + (lane & 3) + 4) * 136 + cN]);
            }
#pragma unroll
            for (int mt = 0; mt < 4; mt++)
#pragma unroll
                for (int nt = 0; nt < 4; nt++)
                    mma_tf32(acc[mt][nt], afr[mt], bfr[nt]);
        }
        __syncthreads();
    }

    // epilogue: C[row][col] = acc + bias[col]
#pragma unroll
    for (int nt = 0; nt < 4; nt++) {
        int c = bcol + wn * 32 + nt * 8 + 2 * (lane & 3);
        float2 bv = *(const float2*)(bias + c);
#pragma unroll
        for (int mt = 0; mt < 4; mt++) {
            int r = brow + wm * 64 + mt * 16 + (lane >> 2);
            float2 o0 = make_float2(acc[mt][nt][0] + bv.x, acc[mt][nt][1] + bv.y);
            float2 o1 = make_float2(acc[mt][nt][2] + bv.x, acc[mt][nt][3] + bv.y);
            *(float2*)(C + (size_t)r * GN + c) = o0;
            *(float2*)(C + (size_t)(r + 8) * GN + c) = o1;
        }
    }
}

__global__ __launch_bounds__(256, 2) void gemm_qkv_kernel(
    const float* __restrict__ X,
    const float* __restrict__ Wq, const float* __restrict__ Wk, const float* __restrict__ Wv,
    const float* __restrict__ bq, const float* __restrict__ bk, const float* __restrict__ bv,
    float* __restrict__ Q, float* __restrict__ K, float* __restrict__ V)
{
    const float* W = (blockIdx.z == 0) ? Wq : (blockIdx.z == 1) ? Wk : Wv;
    const float* b = (blockIdx.z == 0) ? bq : (blockIdx.z == 1) ? bk : bv;
    float*       C = (blockIdx.z == 0) ? Q  : (blockIdx.z == 1) ? K  : V;
    gemm_body(X, W, b, C);
}

__global__ __launch_bounds__(256, 2) void gemm_o_kernel(
    const float* __restrict__ A, const float* __restrict__ W,
    const float* __restrict__ b, float* __restrict__ C)
{
    gemm_body(A, W, b, C);
}

// ---------------------------------------------------------------------------
// Banded attention. One block per (chunk, head, batch). 64 q x 192 k x 64 d.
// V overlays the K smem region after scores -> 70.4KB smem -> 2 blocks/SM.
// ---------------------------------------------------------------------------
#define PADW 68
#define ATTN_SMEM_FLOATS (64*PADW + 192*PADW + 192)

__global__ __launch_bounds__(256) void attn_kernel(const float* __restrict__ maskp)
{
    extern __shared__ float sm[];
    float* Qs  = sm;                       // 64 x 68
    float* Ks  = Qs + 64 * PADW;           // 192 x 68  (reused for V)
    float* vld = Ks + 192 * PADW;          // 192

    const int c = blockIdx.x;
    const int h = blockIdx.y;
    const int b = blockIdx.z;
    const int tid = threadIdx.x;

    const size_t headoff = (size_t)h * HDIM;
    const size_t bbase   = (size_t)b * S_LEN;
    const int base = c * 64 - 64;

    // ---- load Q tile: 64 x 64
#pragma unroll
    for (int it = 0; it < 4; it++) {
        int idx = tid + it * 256;
        int r  = idx >> 4;
        int c4 = (idx & 15) << 2;
        float4 v = *(const float4*)(g_Q + (bbase + c * 64 + r) * HIDDEN + headoff + c4);
        *(float4*)&Qs[r * PADW + c4] = v;
    }
    // ---- load K tile: 192 x 64
#pragma unroll
    for (int it = 0; it < 12; it++) {
        int idx = tid + it * 256;
        int r  = idx >> 4;
        int c4 = (idx & 15) << 2;
        int jg = base + r;
        float4 kv = make_float4(0.f, 0.f, 0.f, 0.f);
        if (jg >= 0 && jg < S_LEN)
            kv = *(const float4*)(g_K + (bbase + jg) * HIDDEN + headoff + c4);
        *(float4*)&Ks[r * PADW + c4] = kv;
    }
    if (tid < 192) {
        int jg = base + tid;
        vld[tid] = (jg >= 0 && jg < S_LEN && maskp[b * S_LEN + jg] > 0.f) ? 1.f : 0.f;
    }
    __syncthreads();

    const int q = tid >> 2;
    const int j = tid & 3;

    // ---- scores
    float sc[48];
#pragma unroll
    for (int kk = 0; kk < 48; kk++) sc[kk] = 0.f;

    const float* Qr = &Qs[q * PADW];
#pragma unroll
    for (int d4 = 0; d4 < 16; d4++) {
        float4 qv = *(const float4*)&Qr[d4 * 4];
#pragma unroll
        for (int kk = 0; kk < 48; kk++) {
            float4 kv = *(const float4*)&Ks[(kk * 4 + j) * PADW + d4 * 4];
            sc[kk] += qv.x * kv.x + qv.y * kv.y + qv.z * kv.z + qv.w * kv.w;
        }
    }

    // ---- mask
    float m = -1e30f;
#pragma unroll
    for (int kk = 0; kk < 48; kk++) {
        int ki = kk * 4 + j;
        bool ok = (ki >= q) && (ki <= q + 128) && (vld[ki] > 0.f);
        sc[kk] = ok ? sc[kk] * 0.125f : -1e9f;
        m = fmaxf(m, sc[kk]);
    }

    __syncthreads();   // all reads of Ks (K-phase) done

    // ---- overlay: load V into the Ks region
#pragma unroll
    for (int it = 0; it < 12; it++) {
        int idx = tid + it * 256;
        int r  = idx >> 4;
        int c4 = (idx & 15) << 2;
        int jg = base + r;
        float4 vv = make_float4(0.f, 0.f, 0.f, 0.f);
        if (jg >= 0 && jg < S_LEN)
            vv = *(const float4*)(g_V + (bbase + jg) * HIDDEN + headoff + c4);
        *(float4*)&Ks[r * PADW + c4] = vv;
    }

    // ---- softmax (register-only, overlaps the V store latency)
    m = fmaxf(m, __shfl_xor_sync(0xffffffffu, m, 1));
    m = fmaxf(m, __shfl_xor_sync(0xffffffffu, m, 2));
    float s = 0.f;
#pragma unroll
    for (int kk = 0; kk < 48; kk++) {
        sc[kk] = __expf(sc[kk] - m);
        s += sc[kk];
    }
    s += __shfl_xor_sync(0xffffffffu, s, 1);
    s += __shfl_xor_sync(0xffffffffu, s, 2);
    const float rinv = 1.f / s;

    __syncthreads();   // V tile ready

    // ---- ctx = P @ V
    float ctx[64];
#pragma unroll
    for (int d = 0; d < 64; d++) ctx[d] = 0.f;

#pragma unroll
    for (int kk = 0; kk < 48; kk++) {
        float p = sc[kk];
        const float* Vr = &Ks[(kk * 4 + j) * PADW];
#pragma unroll
        for (int d4 = 0; d4 < 16; d4++) {
            float4 vv = *(const float4*)&Vr[d4 * 4];
            ctx[d4 * 4 + 0] += p * vv.x;
            ctx[d4 * 4 + 1] += p * vv.y;
            ctx[d4 * 4 + 2] += p * vv.z;
            ctx[d4 * 4 + 3] += p * vv.w;
        }
    }

    // ---- reduce across the 4 threads of each q-group
    float outv[16];
#pragma unroll
    for (int g = 0; g < 4; g++) {
#pragma unroll
        for (int t = 0; t < 16; t++) {
            float v = ctx[g * 16 + t];
            v += __shfl_xor_sync(0xffffffffu, v, 1);
            v += __shfl_xor_sync(0xffffffffu, v, 2);
            if (j == g) outv[t] = v * rinv;
        }
    }

    float* Og = g_ctx + (bbase + c * 64 + q) * HIDDEN + headoff + j * 16;
#pragma unroll
    for (int t4 = 0; t4 < 4; t4++)
        *(float4*)(Og + t4 * 4) = make_float4(outv[t4 * 4 + 0], outv[t4 * 4 + 1],
                                              outv[t4 * 4 + 2], outv[t4 * 4 + 3]);
}

// ---------------------------------------------------------------------------
extern "C" void kernel_launch(void* const* d_in, const int* in_sizes, int n_in,
                              void* d_out, int out_size)
{
    const float* X    = (const float*)d_in[0];
    const float* mask = (const float*)d_in[1];
    const float* Wq   = (const float*)d_in[2];
    const float* bq   = (const float*)d_in[3];
    const float* Wk   = (const float*)d_in[4];
    const float* bk   = (const float*)d_in[5];
    const float* Wv   = (const float*)d_in[6];
    const float* bv   = (const float*)d_in[7];
    const float* Wo   = (const float*)d_in[8];
    const float* bo   = (const float*)d_in[9];
    float* out = (float*)d_out;

    float *qp, *kp, *vp, *cp;
    cudaGetSymbolAddress((void**)&qp, g_Q);
    cudaGetSymbolAddress((void**)&kp, g_K);
    cudaGetSymbolAddress((void**)&vp, g_V);
    cudaGetSymbolAddress((void**)&cp, g_ctx);

    const int attn_smem = ATTN_SMEM_FLOATS * (int)sizeof(float);
    cudaFuncSetAttribute(attn_kernel, cudaFuncAttributeMaxDynamicSharedMemorySize,
                         attn_smem);

    dim3 gblk(256);
    dim3 gqkv(HIDDEN / 128, MROWS / 128, 3);   // 8 x 64 x 3
    gemm_qkv_kernel<<<gqkv, gblk>>>(X, Wq, Wk, Wv, bq, bk, bv, qp, kp, vp);

    dim3 agrid(NCHUNK, NHEAD, BATCH);          // 64 x 16 x 2
    attn_kernel<<<agrid, gblk, attn_smem>>>(mask);

    dim3 go(HIDDEN / 128, MROWS / 128);        // 8 x 64
    gemm_o_kernel<<<go, gblk>>>(cp, Wo, bo, out);
}

// round 3
// speedup vs baseline: 3.0997x; 1.5345x over previous
#include <cuda_runtime.h>
#include <cstdint>

// ---------------------------------------------------------------------------
// LongformerAttention  B=2, S=4096, HID=1024, H=16, D=64, W=64
// Round 3: attention moved to tensor cores (mma.sync tf32, hi/lo-compensated P)
// ---------------------------------------------------------------------------

#define S_LEN   4096
#define HIDDEN  1024
#define NHEAD   16
#define HDIM    64
#define NCHUNK  64
#define BATCH   2
#define MROWS   (BATCH * S_LEN)   // 8192

__device__ float g_Q[(size_t)MROWS * HIDDEN];
__device__ float g_K[(size_t)MROWS * HIDDEN];
__device__ float g_V[(size_t)MROWS * HIDDEN];
__device__ float g_ctx[(size_t)MROWS * HIDDEN];

__device__ __forceinline__ float to_tf32(float x) {
    float y;
    asm("cvt.rna.tf32.f32 %0, %1;" : "=f"(y) : "f"(x));
    return y;
}

__device__ __forceinline__ void mma_tf32(float c[4], const uint32_t a[4], const uint32_t b[2]) {
    asm volatile(
        "mma.sync.aligned.m16n8k8.row.col.f32.tf32.tf32.f32 "
        "{%0,%1,%2,%3}, {%4,%5,%6,%7}, {%8,%9}, {%0,%1,%2,%3};"
        : "+f"(c[0]), "+f"(c[1]), "+f"(c[2]), "+f"(c[3])
        : "r"(a[0]), "r"(a[1]), "r"(a[2]), "r"(a[3]), "r"(b[0]), "r"(b[1]));
}

// ---------------------------------------------------------------------------
// tf32 GEMM (unchanged from R2): C[M,N] = A[M,K] @ B[K,N] + bias[N]
// ---------------------------------------------------------------------------
#define GK 1024
#define GN 1024

__device__ __forceinline__ void gemm_body(
    const float* __restrict__ A, const float* __restrict__ Bm,
    const float* __restrict__ bias, float* __restrict__ C)
{
    __shared__ float As[128 * 36];
    __shared__ float Bs[32 * 136];

    const int tid  = threadIdx.x;
    const int lane = tid & 31;
    const int wid  = tid >> 5;
    const int wm   = wid >> 2;
    const int wn   = wid & 3;
    const int brow = blockIdx.y * 128;
    const int bcol = blockIdx.x * 128;

    float acc[4][4][4];
#pragma unroll
    for (int i = 0; i < 4; i++)
#pragma unroll
        for (int j = 0; j < 4; j++)
#pragma unroll
            for (int t = 0; t < 4; t++) acc[i][j][t] = 0.f;

    const int la_r  = tid >> 3;
    const int la_c4 = (tid & 7) << 2;
    const int lb_c4 = (tid & 31) << 2;

    for (int k0 = 0; k0 < GK; k0 += 32) {
#pragma unroll
        for (int i = 0; i < 4; i++) {
            int r = la_r + i * 32;
            float4 v = *(const float4*)(A + (size_t)(brow + r) * GK + k0 + la_c4);
            float* p = &As[r * 36 + la_c4];
            p[0] = to_tf32(v.x); p[1] = to_tf32(v.y);
            p[2] = to_tf32(v.z); p[3] = to_tf32(v.w);
        }
#pragma unroll
        for (int i = 0; i < 4; i++) {
            int idx = tid + i * 256;
            int kr = idx >> 5;
            float4 v = *(const float4*)(Bm + (size_t)(k0 + kr) * GN + bcol + lb_c4);
            float* p = &Bs[kr * 136 + lb_c4];
            p[0] = to_tf32(v.x); p[1] = to_tf32(v.y);
            p[2] = to_tf32(v.z); p[3] = to_tf32(v.w);
        }
        __syncthreads();

#pragma unroll
        for (int ks = 0; ks < 4; ks++) {
            const int kb = ks * 8;
            uint32_t afr[4][4];
#pragma unroll
            for (int mt = 0; mt < 4; mt++) {
                int r0 = wm * 64 + mt * 16 + (lane >> 2);
                afr[mt][0] = __float_as_uint(As[r0 * 36 + kb + (lane & 3)]);
                afr[mt][1] = __float_as_uint(As[(r0 + 8) * 36 + kb + (lane & 3)]);
                afr[mt][2] = __float_as_uint(As[r0 * 36 + kb + (lane & 3) + 4]);
                afr[mt][3] = __float_as_uint(As[(r0 + 8) * 36 + kb + (lane & 3) + 4]);
            }
            uint32_t bfr[4][2];
#pragma unroll
            for (int nt = 0; nt < 4; nt++) {
                int cN = wn * 32 + nt * 8 + (lane >> 2);
                bfr[nt][0] = __float_as_uint(Bs[(kb + (lane & 3)) * 136 + cN]);
                bfr[nt][1] = __float_as_uint(Bs[(kb + (lane & 3) + 4) * 136 + cN]);
            }
#pragma unroll
            for (int mt = 0; mt < 4; mt++)
#pragma unroll
                for (int nt = 0; nt < 4; nt++)
                    mma_tf32(acc[mt][nt], afr[mt], bfr[nt]);
        }
        __syncthreads();
    }

#pragma unroll
    for (int nt = 0; nt < 4; nt++) {
        int c = bcol + wn * 32 + nt * 8 + 2 * (lane & 3);
        float2 bv = *(const float2*)(bias + c);
#pragma unroll
        for (int mt = 0; mt < 4; mt++) {
            int r = brow + wm * 64 + mt * 16 + (lane >> 2);
            float2 o0 = make_float2(acc[mt][nt][0] + bv.x, acc[mt][nt][1] + bv.y);
            float2 o1 = make_float2(acc[mt][nt][2] + bv.x, acc[mt][nt][3] + bv.y);
            *(float2*)(C + (size_t)r * GN + c) = o0;
            *(float2*)(C + (size_t)(r + 8) * GN + c) = o1;
        }
    }
}

__global__ __launch_bounds__(256, 2) void gemm_qkv_kernel(
    const float* __restrict__ X,
    const float* __restrict__ Wq, const float* __restrict__ Wk, const float* __restrict__ Wv,
    const float* __restrict__ bq, const float* __restrict__ bk, const float* __restrict__ bv,
    float* __restrict__ Q, float* __restrict__ K, float* __restrict__ V)
{
    const float* W = (blockIdx.z == 0) ? Wq : (blockIdx.z == 1) ? Wk : Wv;
    const float* b = (blockIdx.z == 0) ? bq : (blockIdx.z == 1) ? bk : bv;
    float*       C = (blockIdx.z == 0) ? Q  : (blockIdx.z == 1) ? K  : V;
    gemm_body(X, W, b, C);
}

__global__ __launch_bounds__(256, 2) void gemm_o_kernel(
    const float* __restrict__ A, const float* __restrict__ W,
    const float* __restrict__ b, float* __restrict__ C)
{
    gemm_body(A, W, b, C);
}

// ---------------------------------------------------------------------------
// Banded attention, tensor-core version.
// Block = (chunk, head, batch), 256 threads = 8 warps (wm in {0,1}, wn in {0..3}).
// Phase A: S = Q K^T (64x192, K=64). Warp tile 32x48 (mt=2, nt=6).
// Softmax with two smem reduction passes. P stored hi/lo (error-compensated tf32).
// Phase B: ctx = P V (64x64, K=192). Warp tile 32x16 (mt=2, nt=2), 2 MMAs (hi+lo).
// ---------------------------------------------------------------------------
#define PW  68     // stride for Qs/Ks (68 mod 32 = 4 -> conflict-free frags)
#define PPW 196    // stride for Ph/Pl (196 mod 32 = 4 -> conflict-free frags)
#define ATTN_SMEM_FLOATS (64*PW + 192*PW + 2*64*PPW + 192 + 256 + 256)

__global__ __launch_bounds__(256) void attn_kernel(const float* __restrict__ maskp)
{
    extern __shared__ float sm[];
    float* Qs   = sm;                    // 64 x 68 (tf32)
    float* Ks   = Qs + 64 * PW;          // 192 x 68 (K tf32, then V tf32)
    float* Ph   = Ks + 192 * PW;         // 64 x 196 (P hi)
    float* Pl   = Ph + 64 * PPW;         // 64 x 196 (P lo)
    float* vld  = Pl + 64 * PPW;         // 192
    float* redM = vld + 192;             // 4 x 64 row-max partials
    float* redS = redM + 256;            // 4 x 64 row-sum partials

    const int c = blockIdx.x;
    const int h = blockIdx.y;
    const int b = blockIdx.z;
    const int tid  = threadIdx.x;
    const int lane = tid & 31;
    const int wid  = tid >> 5;
    const int wm   = wid >> 2;           // 0..1
    const int wn   = wid & 3;            // 0..3
    const int qq   = lane >> 2;          // quad row 0..7
    const int qk   = lane & 3;           // quad col 0..3

    const size_t headoff = (size_t)h * HDIM;
    const size_t bbase   = (size_t)b * S_LEN;
    const int base = c * 64 - 64;

    // ---- load Q (64x64) and K (192x64) as tf32
#pragma unroll
    for (int it = 0; it < 4; it++) {
        int idx = tid + it * 256;
        int r  = idx >> 4;
        int c4 = (idx & 15) << 2;
        float4 v = *(const float4*)(g_Q + (bbase + c * 64 + r) * HIDDEN + headoff + c4);
        float* p = &Qs[r * PW + c4];
        p[0] = to_tf32(v.x); p[1] = to_tf32(v.y);
        p[2] = to_tf32(v.z); p[3] = to_tf32(v.w);
    }
#pragma unroll
    for (int it = 0; it < 12; it++) {
        int idx = tid + it * 256;
        int r  = idx >> 4;
        int c4 = (idx & 15) << 2;
        int jg = base + r;
        float4 kv = make_float4(0.f, 0.f, 0.f, 0.f);
        if (jg >= 0 && jg < S_LEN)
            kv = *(const float4*)(g_K + (bbase + jg) * HIDDEN + headoff + c4);
        float* p = &Ks[r * PW + c4];
        p[0] = to_tf32(kv.x); p[1] = to_tf32(kv.y);
        p[2] = to_tf32(kv.z); p[3] = to_tf32(kv.w);
    }
    if (tid < 192) {
        int jg = base + tid;
        vld[tid] = (jg >= 0 && jg < S_LEN && maskp[b * S_LEN + jg] > 0.f) ? 1.f : 0.f;
    }
    __syncthreads();

    // ---- Phase A: S = Q K^T  (rows wm*32..+32, cols wn*48..+48)
    float acc[2][6][4];
#pragma unroll
    for (int mt = 0; mt < 2; mt++)
#pragma unroll
        for (int nt = 0; nt < 6; nt++)
#pragma unroll
            for (int t = 0; t < 4; t++) acc[mt][nt][t] = 0.f;

#pragma unroll
    for (int ks = 0; ks < 8; ks++) {
        const int kb = ks * 8;
        uint32_t af[2][4];
#pragma unroll
        for (int mt = 0; mt < 2; mt++) {
            int r0 = wm * 32 + mt * 16 + qq;
            af[mt][0] = __float_as_uint(Qs[r0 * PW + kb + qk]);
            af[mt][1] = __float_as_uint(Qs[(r0 + 8) * PW + kb + qk]);
            af[mt][2] = __float_as_uint(Qs[r0 * PW + kb + qk + 4]);
            af[mt][3] = __float_as_uint(Qs[(r0 + 8) * PW + kb + qk + 4]);
        }
        uint32_t bf[6][2];
#pragma unroll
        for (int nt = 0; nt < 6; nt++) {
            int n = wn * 48 + nt * 8 + qq;
            bf[nt][0] = __float_as_uint(Ks[n * PW + kb + qk]);
            bf[nt][1] = __float_as_uint(Ks[n * PW + kb + qk + 4]);
        }
#pragma unroll
        for (int mt = 0; mt < 2; mt++)
#pragma unroll
            for (int nt = 0; nt < 6; nt++)
                mma_tf32(acc[mt][nt], af[mt], bf[nt]);
    }

    // ---- scale + band/valid mask + row-max partials
    float mrow[2][2];
#pragma unroll
    for (int mt = 0; mt < 2; mt++)
#pragma unroll
        for (int hf = 0; hf < 2; hf++) mrow[mt][hf] = -1e30f;

#pragma unroll
    for (int mt = 0; mt < 2; mt++)
#pragma unroll
        for (int nt = 0; nt < 6; nt++) {
            int colb = wn * 48 + nt * 8 + 2 * qk;
#pragma unroll
            for (int hf = 0; hf < 2; hf++) {
                int row = wm * 32 + mt * 16 + qq + 8 * hf;
#pragma unroll
                for (int e = 0; e < 2; e++) {
                    int col = colb + e;
                    float v = acc[mt][nt][hf * 2 + e] * 0.125f;
                    bool ok = (col >= row) && (col <= row + 128) && (vld[col] > 0.f);
                    v = ok ? v : -1e9f;
                    acc[mt][nt][hf * 2 + e] = v;
                    mrow[mt][hf] = fmaxf(mrow[mt][hf], v);
                }
            }
        }
#pragma unroll
    for (int mt = 0; mt < 2; mt++)
#pragma unroll
        for (int hf = 0; hf < 2; hf++) {
            float m = mrow[mt][hf];
            m = fmaxf(m, __shfl_xor_sync(0xffffffffu, m, 1));
            m = fmaxf(m, __shfl_xor_sync(0xffffffffu, m, 2));
            mrow[mt][hf] = m;
        }
    if (qk == 0) {
#pragma unroll
        for (int mt = 0; mt < 2; mt++)
#pragma unroll
            for (int hf = 0; hf < 2; hf++)
                redM[wn * 64 + wm * 32 + mt * 16 + qq + 8 * hf] = mrow[mt][hf];
    }
    __syncthreads();   // redM ready; all warps done reading K fragments

    // ---- global row max, exp, P hi/lo store, row-sum partials; overlay V
    float gmv[2][2], srow[2][2];
#pragma unroll
    for (int mt = 0; mt < 2; mt++)
#pragma unroll
        for (int hf = 0; hf < 2; hf++) {
            int row = wm * 32 + mt * 16 + qq + 8 * hf;
            float m = fmaxf(fmaxf(redM[row], redM[64 + row]),
                            fmaxf(redM[128 + row], redM[192 + row]));
            gmv[mt][hf] = m;
            srow[mt][hf] = 0.f;
        }

#pragma unroll
    for (int mt = 0; mt < 2; mt++)
#pragma unroll
        for (int nt = 0; nt < 6; nt++) {
            int colb = wn * 48 + nt * 8 + 2 * qk;
#pragma unroll
            for (int hf = 0; hf < 2; hf++) {
                int row = wm * 32 + mt * 16 + qq + 8 * hf;
                float p0 = __expf(acc[mt][nt][hf * 2 + 0] - gmv[mt][hf]);
                float p1 = __expf(acc[mt][nt][hf * 2 + 1] - gmv[mt][hf]);
                srow[mt][hf] += p0 + p1;
                float h0 = to_tf32(p0), h1 = to_tf32(p1);
                *(float2*)&Ph[row * PPW + colb] = make_float2(h0, h1);
                *(float2*)&Pl[row * PPW + colb] = make_float2(to_tf32(p0 - h0),
                                                             to_tf32(p1 - h1));
            }
        }

#pragma unroll
    for (int mt = 0; mt < 2; mt++)
#pragma unroll
        for (int hf = 0; hf < 2; hf++) {
            float s = srow[mt][hf];
            s += __shfl_xor_sync(0xffffffffu, s, 1);
            s += __shfl_xor_sync(0xffffffffu, s, 2);
            srow[mt][hf] = s;
        }
    if (qk == 0) {
#pragma unroll
        for (int mt = 0; mt < 2; mt++)
#pragma unroll
            for (int hf = 0; hf < 2; hf++)
                redS[wn * 64 + wm * 32 + mt * 16 + qq + 8 * hf] = srow[mt][hf];
    }

    // V overlay into Ks (safe: all K reads finished before previous sync)
#pragma unroll
    for (int it = 0; it < 12; it++) {
        int idx = tid + it * 256;
        int r  = idx >> 4;
        int c4 = (idx & 15) << 2;
        int jg = base + r;
        float4 vv = make_float4(0.f, 0.f, 0.f, 0.f);
        if (jg >= 0 && jg < S_LEN)
            vv = *(const float4*)(g_V + (bbase + jg) * HIDDEN + headoff + c4);
        float* p = &Ks[r * PW + c4];
        p[0] = to_tf32(vv.x); p[1] = to_tf32(vv.y);
        p[2] = to_tf32(vv.z); p[3] = to_tf32(vv.w);
    }
    __syncthreads();   // Ph, Pl, redS, V all ready

    // ---- Phase B: ctx = P V  (rows wm*32..+32, cols wn*16..+16, K=192)
    float c2[2][2][4];
#pragma unroll
    for (int mt = 0; mt < 2; mt++)
#pragma unroll
        for (int nt = 0; nt < 2; nt++)
#pragma unroll
            for (int t = 0; t < 4; t++) c2[mt][nt][t] = 0.f;

#pragma unroll
    for (int ks = 0; ks < 24; ks++) {
        const int kb = ks * 8;
        uint32_t ah[2][4], al[2][4];
#pragma unroll
        for (int mt = 0; mt < 2; mt++) {
            int r0 = wm * 32 + mt * 16 + qq;
            ah[mt][0] = __float_as_uint(Ph[r0 * PPW + kb + qk]);
            ah[mt][1] = __float_as_uint(Ph[(r0 + 8) * PPW + kb + qk]);
            ah[mt][2] = __float_as_uint(Ph[r0 * PPW + kb + qk + 4]);
            ah[mt][3] = __float_as_uint(Ph[(r0 + 8) * PPW + kb + qk + 4]);
            al[mt][0] = __float_as_uint(Pl[r0 * PPW + kb + qk]);
            al[mt][1] = __float_as_uint(Pl[(r0 + 8) * PPW + kb + qk]);
            al[mt][2] = __float_as_uint(Pl[r0 * PPW + kb + qk + 4]);
            al[mt][3] = __float_as_uint(Pl[(r0 + 8) * PPW + kb + qk + 4]);
        }
        uint32_t bf[2][2];
#pragma unroll
        for (int nt = 0; nt < 2; nt++) {
            int n = wn * 16 + nt * 8 + qq;
            bf[nt][0] = __float_as_uint(Ks[(kb + qk) * PW + n]);
            bf[nt][1] = __float_as_uint(Ks[(kb + qk + 4) * PW + n]);
        }
#pragma unroll
        for (int mt = 0; mt < 2; mt++)
#pragma unroll
            for (int nt = 0; nt < 2; nt++) {
                mma_tf32(c2[mt][nt], ah[mt], bf[nt]);
                mma_tf32(c2[mt][nt], al[mt], bf[nt]);
            }
    }

    // ---- epilogue: normalize and store
#pragma unroll
    for (int mt = 0; mt < 2; mt++)
#pragma unroll
        for (int hf = 0; hf < 2; hf++) {
            int row = wm * 32 + mt * 16 + qq + 8 * hf;
            float s = redS[row] + redS[64 + row] + redS[128 + row] + redS[192 + row];
            float rinv = 1.f / s;
            float* Og = g_ctx + (bbase + c * 64 + row) * HIDDEN + headoff;
#pragma unroll
            for (int nt = 0; nt < 2; nt++) {
                int col = wn * 16 + nt * 8 + 2 * qk;
                *(float2*)(Og + col) = make_float2(c2[mt][nt][hf * 2 + 0] * rinv,
                                                   c2[mt][nt][hf * 2 + 1] * rinv);
            }
        }
}

// ---------------------------------------------------------------------------
extern "C" void kernel_launch(void* const* d_in, const int* in_sizes, int n_in,
                              void* d_out, int out_size)
{
    const float* X    = (const float*)d_in[0];
    const float* mask = (const float*)d_in[1];
    const float* Wq   = (const float*)d_in[2];
    const float* bq   = (const float*)d_in[3];
    const float* Wk   = (const float*)d_in[4];
    const float* bk   = (const float*)d_in[5];
    const float* Wv   = (const float*)d_in[6];
    const float* bv   = (const float*)d_in[7];
    const float* Wo   = (const float*)d_in[8];
    const float* bo   = (const float*)d_in[9];
    float* out = (float*)d_out;

    float *qp, *kp, *vp, *cp;
    cudaGetSymbolAddress((void**)&qp, g_Q);
    cudaGetSymbolAddress((void**)&kp, g_K);
    cudaGetSymbolAddress((void**)&vp, g_V);
    cudaGetSymbolAddress((void**)&cp, g_ctx);

    const int attn_smem = ATTN_SMEM_FLOATS * (int)sizeof(float);
    cudaFuncSetAttribute(attn_kernel, cudaFuncAttributeMaxDynamicSharedMemorySize,
                         attn_smem);

    dim3 gblk(256);
    dim3 gqkv(HIDDEN / 128, MROWS / 128, 3);   // 8 x 64 x 3
    gemm_qkv_kernel<<<gqkv, gblk>>>(X, Wq, Wk, Wv, bq, bk, bv, qp, kp, vp);

    dim3 agrid(NCHUNK, NHEAD, BATCH);          // 64 x 16 x 2
    attn_kernel<<<agrid, gblk, attn_smem>>>(mask);

    dim3 go(HIDDEN / 128, MROWS / 128);        // 8 x 64
    gemm_o_kernel<<<go, gblk>>>(cp, Wo, bo, out);
}

// round 4
// speedup vs baseline: 3.4410x; 1.1101x over previous
#include <cuda_runtime.h>
#include <cstdint>

// ---------------------------------------------------------------------------
// LongformerAttention  B=2, S=4096, HID=1024, H=16, D=64, W=64
// Round 4: cp.async double-buffered tf32 GEMMs + tf32 pre-rounding pass
// ---------------------------------------------------------------------------

#define S_LEN   4096
#define HIDDEN  1024
#define NHEAD   16
#define HDIM    64
#define NCHUNK  64
#define BATCH   2
#define MROWS   (BATCH * S_LEN)   // 8192

__device__ float g_Q[(size_t)MROWS * HIDDEN];
__device__ float g_K[(size_t)MROWS * HIDDEN];
__device__ float g_V[(size_t)MROWS * HIDDEN];
__device__ float g_ctx[(size_t)MROWS * HIDDEN];
__device__ float g_Xr[(size_t)MROWS * HIDDEN];          // tf32-rounded X
__device__ float g_Wr[4][(size_t)HIDDEN * HIDDEN];      // tf32-rounded Wq,Wk,Wv,Wo

__device__ __forceinline__ float to_tf32(float x) {
    float y;
    asm("cvt.rna.tf32.f32 %0, %1;" : "=f"(y) : "f"(x));
    return y;
}

__device__ __forceinline__ void mma_tf32(float c[4], const uint32_t a[4], const uint32_t b[2]) {
    asm volatile(
        "mma.sync.aligned.m16n8k8.row.col.f32.tf32.tf32.f32 "
        "{%0,%1,%2,%3}, {%4,%5,%6,%7}, {%8,%9}, {%0,%1,%2,%3};"
        : "+f"(c[0]), "+f"(c[1]), "+f"(c[2]), "+f"(c[3])
        : "r"(a[0]), "r"(a[1]), "r"(a[2]), "r"(a[3]), "r"(b[0]), "r"(b[1]));
}

__device__ __forceinline__ void cp_async16(uint32_t dst, const void* src) {
    asm volatile("cp.async.cg.shared.global [%0], [%1], 16;\n"
                 :: "r"(dst), "l"(src));
}

// ---------------------------------------------------------------------------
// tf32 pre-rounding pass (inputs to cp.async GEMMs must be pre-rounded)
// ---------------------------------------------------------------------------
__global__ __launch_bounds__(256) void round_tf32_kernel(
    const float* __restrict__ in, float* __restrict__ out, int n4)
{
    int i = blockIdx.x * blockDim.x + threadIdx.x;
    if (i < n4) {
        float4 v = ((const float4*)in)[i];
        v.x = to_tf32(v.x); v.y = to_tf32(v.y);
        v.z = to_tf32(v.z); v.w = to_tf32(v.w);
        ((float4*)out)[i] = v;
    }
}

// ---------------------------------------------------------------------------
// Pipelined tf32 GEMM: C[M,N] = A[M,K] @ B[K,N] + bias[N]
// Block tile 128x128, BK=32, 2-stage cp.async double buffer.
// 256 threads (8 warps, 2x4), warp tile 64x32.
// As[m][k] stride 36 (conflict-free), Bs[k][n] stride 136 (conflict-free).
// A and B must be tf32-pre-rounded.
// ---------------------------------------------------------------------------
#define GK 1024
#define GN 1024
#define AS_STRIDE 36
#define BS_STRIDE 136
#define AS_SIZE (128 * AS_STRIDE)   // 4608 floats
#define BS_SIZE (32 * BS_STRIDE)    // 4352 floats
#define GEMM_SMEM_BYTES (2 * (AS_SIZE + BS_SIZE) * (int)sizeof(float))  // 71680

__device__ __forceinline__ void gemm_body_pipe(
    const float* __restrict__ A, const float* __restrict__ Bm,
    const float* __restrict__ bias, float* __restrict__ C, float* sm)
{
    float* As0 = sm;                       // 2 x 4608
    float* Bs0 = sm + 2 * AS_SIZE;         // 2 x 4352

    const int tid  = threadIdx.x;
    const int lane = tid & 31;
    const int wid  = tid >> 5;
    const int wm   = wid >> 2;
    const int wn   = wid & 3;
    const int brow = blockIdx.y * 128;
    const int bcol = blockIdx.x * 128;

    const int la_r  = tid >> 3;            // 0..31
    const int la_c4 = (tid & 7) << 2;      // 0..28
    const int lb_c4 = (tid & 31) << 2;     // 0..124

    float acc[4][4][4];
#pragma unroll
    for (int i = 0; i < 4; i++)
#pragma unroll
        for (int j = 0; j < 4; j++)
#pragma unroll
            for (int t = 0; t < 4; t++) acc[i][j][t] = 0.f;

    // ---- async tile-load issue for stage buffer `buf`, K-offset k0
    auto issue = [&](int buf, int k0) {
        float* Asb = As0 + buf * AS_SIZE;
        float* Bsb = Bs0 + buf * BS_SIZE;
#pragma unroll
        for (int i = 0; i < 4; i++) {
            int r = la_r + i * 32;
            uint32_t dst = (uint32_t)__cvta_generic_to_shared(Asb + r * AS_STRIDE + la_c4);
            cp_async16(dst, A + (size_t)(brow + r) * GK + k0 + la_c4);
        }
#pragma unroll
        for (int i = 0; i < 4; i++) {
            int idx = tid + i * 256;
            int kr = idx >> 5;
            uint32_t dst = (uint32_t)__cvta_generic_to_shared(Bsb + kr * BS_STRIDE + lb_c4);
            cp_async16(dst, Bm + (size_t)(k0 + kr) * GN + bcol + lb_c4);
        }
        asm volatile("cp.async.commit_group;\n" ::: "memory");
    };

    issue(0, 0);

    for (int k0 = 0; k0 < GK; k0 += 32) {
        const int buf = (k0 >> 5) & 1;
        if (k0 + 32 < GK) {
            issue(buf ^ 1, k0 + 32);
            asm volatile("cp.async.wait_group 1;\n" ::: "memory");
        } else {
            asm volatile("cp.async.wait_group 0;\n" ::: "memory");
        }
        __syncthreads();

        const float* Asb = As0 + buf * AS_SIZE;
        const float* Bsb = Bs0 + buf * BS_SIZE;

#pragma unroll
        for (int ks = 0; ks < 4; ks++) {
            const int kb = ks * 8;
            uint32_t afr[4][4];
#pragma unroll
            for (int mt = 0; mt < 4; mt++) {
                int r0 = wm * 64 + mt * 16 + (lane >> 2);
                afr[mt][0] = __float_as_uint(Asb[r0 * AS_STRIDE + kb + (lane & 3)]);
                afr[mt][1] = __float_as_uint(Asb[(r0 + 8) * AS_STRIDE + kb + (lane & 3)]);
                afr[mt][2] = __float_as_uint(Asb[r0 * AS_STRIDE + kb + (lane & 3) + 4]);
                afr[mt][3] = __float_as_uint(Asb[(r0 + 8) * AS_STRIDE + kb + (lane & 3) + 4]);
            }
            uint32_t bfr[4][2];
#pragma unroll
            for (int nt = 0; nt < 4; nt++) {
                int cN = wn * 32 + nt * 8 + (lane >> 2);
                bfr[nt][0] = __float_as_uint(Bsb[(kb + (lane & 3)) * BS_STRIDE + cN]);
                bfr[nt][1] = __float_as_uint(Bsb[(kb + (lane & 3) + 4) * BS_STRIDE + cN]);
            }
#pragma unroll
            for (int mt = 0; mt < 4; mt++)
#pragma unroll
                for (int nt = 0; nt < 4; nt++)
                    mma_tf32(acc[mt][nt], afr[mt], bfr[nt]);
        }
        __syncthreads();
    }

#pragma unroll
    for (int nt = 0; nt < 4; nt++) {
        int c = bcol + wn * 32 + nt * 8 + 2 * (lane & 3);
        float2 bv = *(const float2*)(bias + c);
#pragma unroll
        for (int mt = 0; mt < 4; mt++) {
            int r = brow + wm * 64 + mt * 16 + (lane >> 2);
            float2 o0 = make_float2(acc[mt][nt][0] + bv.x, acc[mt][nt][1] + bv.y);
            float2 o1 = make_float2(acc[mt][nt][2] + bv.x, acc[mt][nt][3] + bv.y);
            *(float2*)(C + (size_t)r * GN + c) = o0;
            *(float2*)(C + (size_t)(r + 8) * GN + c) = o1;
        }
    }
}

__global__ __launch_bounds__(256, 2) void gemm_qkv_kernel(
    const float* __restrict__ X,
    const float* __restrict__ Wq, const float* __restrict__ Wk, const float* __restrict__ Wv,
    const float* __restrict__ bq, const float* __restrict__ bk, const float* __restrict__ bv,
    float* __restrict__ Q, float* __restrict__ K, float* __restrict__ V)
{
    extern __shared__ float smg[];
    const float* W = (blockIdx.z == 0) ? Wq : (blockIdx.z == 1) ? Wk : Wv;
    const float* b = (blockIdx.z == 0) ? bq : (blockIdx.z == 1) ? bk : bv;
    float*       C = (blockIdx.z == 0) ? Q  : (blockIdx.z == 1) ? K  : V;
    gemm_body_pipe(X, W, b, C, smg);
}

__global__ __launch_bounds__(256, 2) void gemm_o_kernel(
    const float* __restrict__ A, const float* __restrict__ W,
    const float* __restrict__ b, float* __restrict__ C)
{
    extern __shared__ float smg[];
    gemm_body_pipe(A, W, b, C, smg);
}

// ---------------------------------------------------------------------------
// Banded attention, tensor-core version (unchanged from R3 except the
// epilogue stores tf32-rounded ctx so the O-projection can cp.async raw).
// ---------------------------------------------------------------------------
#define PW  68
#define PPW 196
#define ATTN_SMEM_FLOATS (64*PW + 192*PW + 2*64*PPW + 192 + 256 + 256)

__global__ __launch_bounds__(256) void attn_kernel(const float* __restrict__ maskp)
{
    extern __shared__ float sm[];
    float* Qs   = sm;                    // 64 x 68
    float* Ks   = Qs + 64 * PW;          // 192 x 68 (K then V)
    float* Ph   = Ks + 192 * PW;         // 64 x 196
    float* Pl   = Ph + 64 * PPW;         // 64 x 196
    float* vld  = Pl + 64 * PPW;         // 192
    float* redM = vld + 192;             // 256
    float* redS = redM + 256;            // 256

    const int c = blockIdx.x;
    const int h = blockIdx.y;
    const int b = blockIdx.z;
    const int tid  = threadIdx.x;
    const int lane = tid & 31;
    const int wid  = tid >> 5;
    const int wm   = wid >> 2;
    const int wn   = wid & 3;
    const int qq   = lane >> 2;
    const int qk   = lane & 3;

    const size_t headoff = (size_t)h * HDIM;
    const size_t bbase   = (size_t)b * S_LEN;
    const int base = c * 64 - 64;

#pragma unroll
    for (int it = 0; it < 4; it++) {
        int idx = tid + it * 256;
        int r  = idx >> 4;
        int c4 = (idx & 15) << 2;
        float4 v = *(const float4*)(g_Q + (bbase + c * 64 + r) * HIDDEN + headoff + c4);
        float* p = &Qs[r * PW + c4];
        p[0] = to_tf32(v.x); p[1] = to_tf32(v.y);
        p[2] = to_tf32(v.z); p[3] = to_tf32(v.w);
    }
#pragma unroll
    for (int it = 0; it < 12; it++) {
        int idx = tid + it * 256;
        int r  = idx >> 4;
        int c4 = (idx & 15) << 2;
        int jg = base + r;
        float4 kv = make_float4(0.f, 0.f, 0.f, 0.f);
        if (jg >= 0 && jg < S_LEN)
            kv = *(const float4*)(g_K + (bbase + jg) * HIDDEN + headoff + c4);
        float* p = &Ks[r * PW + c4];
        p[0] = to_tf32(kv.x); p[1] = to_tf32(kv.y);
        p[2] = to_tf32(kv.z); p[3] = to_tf32(kv.w);
    }
    if (tid < 192) {
        int jg = base + tid;
        vld[tid] = (jg >= 0 && jg < S_LEN && maskp[b * S_LEN + jg] > 0.f) ? 1.f : 0.f;
    }
    __syncthreads();

    // ---- Phase A: S = Q K^T
    float acc[2][6][4];
#pragma unroll
    for (int mt = 0; mt < 2; mt++)
#pragma unroll
        for (int nt = 0; nt < 6; nt++)
#pragma unroll
            for (int t = 0; t < 4; t++) acc[mt][nt][t] = 0.f;

#pragma unroll
    for (int ks = 0; ks < 8; ks++) {
        const int kb = ks * 8;
        uint32_t af[2][4];
#pragma unroll
        for (int mt = 0; mt < 2; mt++) {
            int r0 = wm * 32 + mt * 16 + qq;
            af[mt][0] = __float_as_uint(Qs[r0 * PW + kb + qk]);
            af[mt][1] = __float_as_uint(Qs[(r0 + 8) * PW + kb + qk]);
            af[mt][2] = __float_as_uint(Qs[r0 * PW + kb + qk + 4]);
            af[mt][3] = __float_as_uint(Qs[(r0 + 8) * PW + kb + qk + 4]);
        }
        uint32_t bf[6][2];
#pragma unroll
        for (int nt = 0; nt < 6; nt++) {
            int n = wn * 48 + nt * 8 + qq;
            bf[nt][0] = __float_as_uint(Ks[n * PW + kb + qk]);
            bf[nt][1] = __float_as_uint(Ks[n * PW + kb + qk + 4]);
        }
#pragma unroll
        for (int mt = 0; mt < 2; mt++)
#pragma unroll
            for (int nt = 0; nt < 6; nt++)
                mma_tf32(acc[mt][nt], af[mt], bf[nt]);
    }

    // ---- scale + mask + row-max partials
    float mrow[2][2];
#pragma unroll
    for (int mt = 0; mt < 2; mt++)
#pragma unroll
        for (int hf = 0; hf < 2; hf++) mrow[mt][hf] = -1e30f;

#pragma unroll
    for (int mt = 0; mt < 2; mt++)
#pragma unroll
        for (int nt = 0; nt < 6; nt++) {
            int colb = wn * 48 + nt * 8 + 2 * qk;
#pragma unroll
            for (int hf = 0; hf < 2; hf++) {
                int row = wm * 32 + mt * 16 + qq + 8 * hf;
#pragma unroll
                for (int e = 0; e < 2; e++) {
                    int col = colb + e;
                    float v = acc[mt][nt][hf * 2 + e] * 0.125f;
                    bool ok = (col >= row) && (col <= row + 128) && (vld[col] > 0.f);
                    v = ok ? v : -1e9f;
                    acc[mt][nt][hf * 2 + e] = v;
                    mrow[mt][hf] = fmaxf(mrow[mt][hf], v);
                }
            }
        }
#pragma unroll
    for (int mt = 0; mt < 2; mt++)
#pragma unroll
        for (int hf = 0; hf < 2; hf++) {
            float m = mrow[mt][hf];
            m = fmaxf(m, __shfl_xor_sync(0xffffffffu, m, 1));
            m = fmaxf(m, __shfl_xor_sync(0xffffffffu, m, 2));
            mrow[mt][hf] = m;
        }
    if (qk == 0) {
#pragma unroll
        for (int mt = 0; mt < 2; mt++)
#pragma unroll
            for (int hf = 0; hf < 2; hf++)
                redM[wn * 64 + wm * 32 + mt * 16 + qq + 8 * hf] = mrow[mt][hf];
    }
    __syncthreads();

    // ---- global max, exp, P hi/lo, row sums; overlay V
    float gmv[2][2], srow[2][2];
#pragma unroll
    for (int mt = 0; mt < 2; mt++)
#pragma unroll
        for (int hf = 0; hf < 2; hf++) {
            int row = wm * 32 + mt * 16 + qq + 8 * hf;
            float m = fmaxf(fmaxf(redM[row], redM[64 + row]),
                            fmaxf(redM[128 + row], redM[192 + row]));
            gmv[mt][hf] = m;
            srow[mt][hf] = 0.f;
        }

#pragma unroll
    for (int mt = 0; mt < 2; mt++)
#pragma unroll
        for (int nt = 0; nt < 6; nt++) {
            int colb = wn * 48 + nt * 8 + 2 * qk;
#pragma unroll
            for (int hf = 0; hf < 2; hf++) {
                int row = wm * 32 + mt * 16 + qq + 8 * hf;
                float p0 = __expf(acc[mt][nt][hf * 2 + 0] - gmv[mt][hf]);
                float p1 = __expf(acc[mt][nt][hf * 2 + 1] - gmv[mt][hf]);
                srow[mt][hf] += p0 + p1;
                float h0 = to_tf32(p0), h1 = to_tf32(p1);
                *(float2*)&Ph[row * PPW + colb] = make_float2(h0, h1);
                *(float2*)&Pl[row * PPW + colb] = make_float2(to_tf32(p0 - h0),
                                                             to_tf32(p1 - h1));
            }
        }

#pragma unroll
    for (int mt = 0; mt < 2; mt++)
#pragma unroll
        for (int hf = 0; hf < 2; hf++) {
            float s = srow[mt][hf];
            s += __shfl_xor_sync(0xffffffffu, s, 1);
            s += __shfl_xor_sync(0xffffffffu, s, 2);
            srow[mt][hf] = s;
        }
    if (qk == 0) {
#pragma unroll
        for (int mt = 0; mt < 2; mt++)
#pragma unroll
            for (int hf = 0; hf < 2; hf++)
                redS[wn * 64 + wm * 32 + mt * 16 + qq + 8 * hf] = srow[mt][hf];
    }

#pragma unroll
    for (int it = 0; it < 12; it++) {
        int idx = tid + it * 256;
        int r  = idx >> 4;
        int c4 = (idx & 15) << 2;
        int jg = base + r;
        float4 vv = make_float4(0.f, 0.f, 0.f, 0.f);
        if (jg >= 0 && jg < S_LEN)
            vv = *(const float4*)(g_V + (bbase + jg) * HIDDEN + headoff + c4);
        float* p = &Ks[r * PW + c4];
        p[0] = to_tf32(vv.x); p[1] = to_tf32(vv.y);
        p[2] = to_tf32(vv.z); p[3] = to_tf32(vv.w);
    }
    __syncthreads();

    // ---- Phase B: ctx = P V
    float c2[2][2][4];
#pragma unroll
    for (int mt = 0; mt < 2; mt++)
#pragma unroll
        for (int nt = 0; nt < 2; nt++)
#pragma unroll
            for (int t = 0; t < 4; t++) c2[mt][nt][t] = 0.f;

#pragma unroll
    for (int ks = 0; ks < 24; ks++) {
        const int kb = ks * 8;
        uint32_t ah[2][4], al[2][4];
#pragma unroll
        for (int mt = 0; mt < 2; mt++) {
            int r0 = wm * 32 + mt * 16 + qq;
            ah[mt][0] = __float_as_uint(Ph[r0 * PPW + kb + qk]);
            ah[mt][1] = __float_as_uint(Ph[(r0 + 8) * PPW + kb + qk]);
            ah[mt][2] = __float_as_uint(Ph[r0 * PPW + kb + qk + 4]);
            ah[mt][3] = __float_as_uint(Ph[(r0 + 8) * PPW + kb + qk + 4]);
            al[mt][0] = __float_as_uint(Pl[r0 * PPW + kb + qk]);
            al[mt][1] = __float_as_uint(Pl[(r0 + 8) * PPW + kb + qk]);
            al[mt][2] = __float_as_uint(Pl[r0 * PPW + kb + qk + 4]);
            al[mt][3] = __float_as_uint(Pl[(r0 + 8) * PPW + kb + qk + 4]);
        }
        uint32_t bf[2][2];
#pragma unroll
        for (int nt = 0; nt < 2; nt++) {
            int n = wn * 16 + nt * 8 + qq;
            bf[nt][0] = __float_as_uint(Ks[(kb + qk) * PW + n]);
            bf[nt][1] = __float_as_uint(Ks[(kb + qk + 4) * PW + n]);
        }
#pragma unroll
        for (int mt = 0; mt < 2; mt++)
#pragma unroll
            for (int nt = 0; nt < 2; nt++) {
                mma_tf32(c2[mt][nt], ah[mt], bf[nt]);
                mma_tf32(c2[mt][nt], al[mt], bf[nt]);
            }
    }

    // ---- epilogue: normalize, tf32-round (feeds cp.async O-proj), store
#pragma unroll
    for (int mt = 0; mt < 2; mt++)
#pragma unroll
        for (int hf = 0; hf < 2; hf++) {
            int row = wm * 32 + mt * 16 + qq + 8 * hf;
            float s = redS[row] + redS[64 + row] + redS[128 + row] + redS[192 + row];
            float rinv = 1.f / s;
            float* Og = g_ctx + (bbase + c * 64 + row) * HIDDEN + headoff;
#pragma unroll
            for (int nt = 0; nt < 2; nt++) {
                int col = wn * 16 + nt * 8 + 2 * qk;
                *(float2*)(Og + col) = make_float2(
                    to_tf32(c2[mt][nt][hf * 2 + 0] * rinv),
                    to_tf32(c2[mt][nt][hf * 2 + 1] * rinv));
            }
        }
}

// ---------------------------------------------------------------------------
extern "C" void kernel_launch(void* const* d_in, const int* in_sizes, int n_in,
                              void* d_out, int out_size)
{
    const float* X    = (const float*)d_in[0];
    const float* mask = (const float*)d_in[1];
    const float* Wq   = (const float*)d_in[2];
    const float* bq   = (const float*)d_in[3];
    const float* Wk   = (const float*)d_in[4];
    const float* bk   = (const float*)d_in[5];
    const float* Wv   = (const float*)d_in[6];
    const float* bv   = (const float*)d_in[7];
    const float* Wo   = (const float*)d_in[8];
    const float* bo   = (const float*)d_in[9];
    float* out = (float*)d_out;

    float *qp, *kp, *vp, *cp, *xrp, *wrp;
    cudaGetSymbolAddress((void**)&qp, g_Q);
    cudaGetSymbolAddress((void**)&kp, g_K);
    cudaGetSymbolAddress((void**)&vp, g_V);
    cudaGetSymbolAddress((void**)&cp, g_ctx);
    cudaGetSymbolAddress((void**)&xrp, g_Xr);
    cudaGetSymbolAddress((void**)&wrp, g_Wr);
    float* wq_r = wrp;
    float* wk_r = wrp + (size_t)HIDDEN * HIDDEN;
    float* wv_r = wrp + 2 * (size_t)HIDDEN * HIDDEN;
    float* wo_r = wrp + 3 * (size_t)HIDDEN * HIDDEN;

    const int attn_smem = ATTN_SMEM_FLOATS * (int)sizeof(float);
    cudaFuncSetAttribute(attn_kernel, cudaFuncAttributeMaxDynamicSharedMemorySize,
                         attn_smem);
    cudaFuncSetAttribute(gemm_qkv_kernel, cudaFuncAttributeMaxDynamicSharedMemorySize,
                         GEMM_SMEM_BYTES);
    cudaFuncSetAttribute(gemm_o_kernel, cudaFuncAttributeMaxDynamicSharedMemorySize,
                         GEMM_SMEM_BYTES);

    // ---- tf32 pre-rounding (X + 4 weights)
    const int xN4 = MROWS * HIDDEN / 4;          // 2097152
    const int wN4 = HIDDEN * HIDDEN / 4;         // 262144
    round_tf32_kernel<<<(xN4 + 255) / 256, 256>>>(X, xrp, xN4);
    round_tf32_kernel<<<(wN4 + 255) / 256, 256>>>(Wq, wq_r, wN4);
    round_tf32_kernel<<<(wN4 + 255) / 256, 256>>>(Wk, wk_r, wN4);
    round_tf32_kernel<<<(wN4 + 255) / 256, 256>>>(Wv, wv_r, wN4);
    round_tf32_kernel<<<(wN4 + 255) / 256, 256>>>(Wo, wo_r, wN4);

    dim3 gblk(256);
    dim3 gqkv(HIDDEN / 128, MROWS / 128, 3);
    gemm_qkv_kernel<<<gqkv, gblk, GEMM_SMEM_BYTES>>>(xrp, wq_r, wk_r, wv_r,
                                                     bq, bk, bv, qp, kp, vp);

    dim3 agrid(NCHUNK, NHEAD, BATCH);
    attn_kernel<<<agrid, gblk, attn_smem>>>(mask);

    dim3 go(HIDDEN / 128, MROWS / 128);
    gemm_o_kernel<<<go, gblk, GEMM_SMEM_BYTES>>>(cp, wo_r, bo, out);
}